// round 1
// baseline (speedup 1.0000x reference)
#include <cuda_runtime.h>

// gcnmask: N=50000 nodes, DEG=16 edges/node (edge_dst = repeat(arange(N),16) — structural),
// F=128 features.
//
// Factored algorithm:
//   cproj = x @ Wm[0:128]      (per node, replaces per-edge "cen" half of mask MLP)
//   nproj = x @ Wm[128:256]    (per node, replaces per-edge "nei" half)
//   per node n (edges e in [16n,16n+16)):
//     agg    = sum_e sigmoid(cproj[n] + nproj[src_e]) * x[src_e]
//     x_new  = x[n] + agg
//     support[n] = x_new @ weight          (fused, x_new rows staged in smem)
//   out[n] = bias + sum_e adj[e] * support[src_e]

#define NN   50000
#define FF   128
#define DEG  16
#define R1   16   // rows per block, k_proj       (50000/16 = 3125 exact)
#define R2   8    // rows per block, k2/k3        (50000/8  = 6250 exact)

// Scratch (no cudaMalloc allowed) — 3 x 25.6 MB
__device__ float g_cproj[NN * FF];
__device__ float g_nproj[NN * FF];
__device__ float g_support[NN * FF];

// ---- packed f32x2 helpers (FFMA2: 2x fp32 FMA throughput on sm_103a) ----
__device__ __forceinline__ unsigned long long pack2(float lo, float hi) {
    unsigned long long r;
    asm("mov.b64 %0, {%1, %2};" : "=l"(r) : "f"(lo), "f"(hi));
    return r;
}
__device__ __forceinline__ void fma2(unsigned long long& d,
                                     unsigned long long a,
                                     unsigned long long b) {
    asm("fma.rn.f32x2 %0, %1, %2, %0;" : "+l"(d) : "l"(a), "l"(b));
}
__device__ __forceinline__ float redu2(unsigned long long v) {
    float lo, hi;
    asm("mov.b64 {%0, %1}, %2;" : "=f"(lo), "=f"(hi) : "l"(v));
    return lo + hi;
}

// ============================================================================
// K1: cproj / nproj — x[N,128] @ Wm_top and x @ Wm_bot.
// Block = 128 threads (thread j = output column), 16 rows per block.
// k-dim packed in pairs via fma.rn.f32x2; x rows broadcast from smem.
// ============================================================================
__global__ __launch_bounds__(128) void k_proj(const float* __restrict__ x,
                                              const float* __restrict__ wm) {
    __shared__ float xs[R1][FF];
    const int j = threadIdx.x;
    const int row0 = blockIdx.x * R1;

#pragma unroll
    for (int r = 0; r < R1; ++r)
        xs[r][j] = x[(row0 + r) * FF + j];
    __syncthreads();

    unsigned long long accc[R1], accn[R1];
#pragma unroll
    for (int r = 0; r < R1; ++r) { accc[r] = 0ull; accn[r] = 0ull; }

    const unsigned long long* xs2 =
        reinterpret_cast<const unsigned long long*>(&xs[0][0]);

#pragma unroll 2
    for (int k = 0; k < FF; k += 2) {
        const unsigned long long wc2 =
            pack2(wm[k * FF + j], wm[(k + 1) * FF + j]);
        const unsigned long long wn2 =
            pack2(wm[(FF + k) * FF + j], wm[(FF + k + 1) * FF + j]);
        const int p = k >> 1;
#pragma unroll
        for (int r = 0; r < R1; ++r) {
            const unsigned long long xv = xs2[r * (FF / 2) + p];  // LDS.64 broadcast
            fma2(accc[r], xv, wc2);
            fma2(accn[r], xv, wn2);
        }
    }

#pragma unroll
    for (int r = 0; r < R1; ++r) {
        g_cproj[(row0 + r) * FF + j] = redu2(accc[r]);
        g_nproj[(row0 + r) * FF + j] = redu2(accn[r]);
    }
}

// ============================================================================
// K2 (fused): per-node edge gather + sigmoid mask + agg -> x_new (smem) ->
//             support = x_new @ weight. 8 nodes per block of 128 threads.
// ============================================================================
__global__ __launch_bounds__(128) void k_agg_support(const float* __restrict__ x,
                                                     const float* __restrict__ w,
                                                     const int* __restrict__ esrc) {
    __shared__ float xs[R2][FF];
    const int j = threadIdx.x;
    const int base = blockIdx.x * R2;

#pragma unroll
    for (int r = 0; r < R2; ++r) {
        const int n = base + r;
        const float cp = g_cproj[n * FF + j];
        const int* es = esrc + n * DEG;
        float agg = 0.f;
#pragma unroll
        for (int e = 0; e < DEG; ++e) {
            const int s = es[e];                         // uniform broadcast load
            const float np = __ldg(&g_nproj[s * FF + j]); // L2-resident gather
            const float xv = __ldg(&x[s * FF + j]);       // L2-resident gather
            const float m = __fdividef(1.f, 1.f + __expf(-(cp + np)));
            agg = fmaf(m, xv, agg);
        }
        xs[r][j] = x[n * FF + j] + agg;  // x_new row staged for the GEMM
    }
    __syncthreads();

    unsigned long long acc[R2];
#pragma unroll
    for (int r = 0; r < R2; ++r) acc[r] = 0ull;

    const unsigned long long* xs2 =
        reinterpret_cast<const unsigned long long*>(&xs[0][0]);

#pragma unroll 2
    for (int k = 0; k < FF; k += 2) {
        const unsigned long long w2 = pack2(w[k * FF + j], w[(k + 1) * FF + j]);
        const int p = k >> 1;
#pragma unroll
        for (int r = 0; r < R2; ++r)
            fma2(acc[r], xs2[r * (FF / 2) + p], w2);
    }

#pragma unroll
    for (int r = 0; r < R2; ++r)
        g_support[(base + r) * FF + j] = redu2(acc[r]);
}

// ============================================================================
// K3: out[n] = bias + sum_e adj[e] * support[src_e]. 8 nodes per block.
// ============================================================================
__global__ __launch_bounds__(128) void k_out(const float* __restrict__ adj,
                                             const int* __restrict__ esrc,
                                             const float* __restrict__ bias,
                                             float* __restrict__ out) {
    const int j = threadIdx.x;
    const int base = blockIdx.x * R2;
    const float b = bias[j];

#pragma unroll
    for (int r = 0; r < R2; ++r) {
        const int n = base + r;
        const int* es = esrc + n * DEG;
        const float* av = adj + n * DEG;
        float acc = b;
#pragma unroll
        for (int e = 0; e < DEG; ++e) {
            const int s = es[e];
            acc = fmaf(av[e], __ldg(&g_support[s * FF + j]), acc);
        }
        out[n * FF + j] = acc;
    }
}

// ============================================================================
extern "C" void kernel_launch(void* const* d_in, const int* in_sizes, int n_in,
                              void* d_out, int out_size) {
    const float* x    = (const float*)d_in[0];  // [N,128]
    const float* w    = (const float*)d_in[1];  // [128,128]
    const float* bias = (const float*)d_in[2];  // [128]
    const float* wm   = (const float*)d_in[3];  // [256,128]
    const float* adj  = (const float*)d_in[4];  // [E]
    const int*   esrc = (const int*)d_in[5];    // [E]
    // d_in[6] = edge_dst: structurally repeat(arange(N),16) — exploited, not read.
    float* out = (float*)d_out;

    k_proj<<<NN / R1, 128>>>(x, wm);
    k_agg_support<<<NN / R2, 128>>>(x, w, esrc);
    k_out<<<NN / R2, 128>>>(adj, esrc, bias, out);
}